// round 17
// baseline (speedup 1.0000x reference)
#include <cuda_runtime.h>
#include <cuda_fp16.h>
#include <math.h>

// ---------------- problem constants ----------------
#define BB 64
#define NN 431
#define CC 256
#define HH 56
#define WW 56
#define HW (HH*WW)            // 3136
#define NPTS (BB*NN)          // 27584
#define TILE_P 48
#define FTILES 575            // ceil(27584/48)
#define TBLOCKS 3584          // 64 images x 8 ch-groups x 7 px-groups
#define GRID_TOTAL (TBLOCKS + FTILES)   // 4159
#define THREADS 256

// ---------------- fused smem map (byte offsets) ----------------
#define SM_FEAT 0                        // feat [48][256] fp16 stride 512 swz (24KB)
#define SM_Y0   24576                    // y0 [48][128] stride 256 (12KB); y1/params alias
#define SM_Y1   SM_Y0
#define SM_BUF  36864                    // 2 x 16KB weight double-buffer
#define SM_W2   69632                    // W2 [8][320] stride 640 (5KB)
#define SM_TOTAL 74752                   // -> 2 blocks/SM
#define PRM_W   SM_Y0                    // float [4][48]
#define PRM_OFF (SM_Y0 + 768)            // int   [4][48]

// ---------------- global scratch ----------------
__device__ __align__(16) unsigned char g_W0s[4*16384];  // 4 chunks [128o][64k] s128 swz
__device__ __align__(16) unsigned char g_W1s[3*16384];  // 3 chunks [64o][128k] s256 swz
__device__ __align__(16) unsigned char g_W2s[8*320*2];  // [8o][320k] s640, rows 5..7 zero
__device__ __half g_sfT[(size_t)BB * HW * CC];          // (B, HW, C) fp16
__device__ int g_done[BB];               // transpose blocks completed per image (target 56)
__device__ int g_prep;                   // weight-prep blocks completed (target 234)

// ---------------- helpers ----------------
__device__ __forceinline__ int tile_off(int r, int k, int S) {
    int c16 = k >> 3;
    return r * S + ((((c16 & ~7) | ((c16 ^ r) & 7))) << 4) + ((k & 7) << 1);
}
__device__ __forceinline__ unsigned smem_u32(const void* p) {
    unsigned a;
    asm("{ .reg .u64 t; cvta.to.shared.u64 t, %1; cvt.u32.u64 %0, t; }" : "=r"(a) : "l"(p));
    return a;
}
__device__ __forceinline__ void cp_async16(unsigned sdst, const void* gsrc) {
    asm volatile("cp.async.cg.shared.global [%0], [%1], 16;" :: "r"(sdst), "l"(gsrc));
}
__device__ __forceinline__ void stage16k(unsigned sdst, const unsigned char* gsrc, int tid) {
    #pragma unroll
    for (int i = 0; i < 4; i++)
        cp_async16(sdst + (tid + i * 256) * 16, gsrc + (tid + i * 256) * 16);
    asm volatile("cp.async.commit_group;");
}
__device__ __forceinline__ void ldm_x4(unsigned r[4], unsigned addr) {
    asm volatile("ldmatrix.sync.aligned.m8n8.x4.shared.b16 {%0,%1,%2,%3}, [%4];"
                 : "=r"(r[0]), "=r"(r[1]), "=r"(r[2]), "=r"(r[3]) : "r"(addr));
}
__device__ __forceinline__ void ldm_x2(unsigned r[2], unsigned addr) {
    asm volatile("ldmatrix.sync.aligned.m8n8.x2.shared.b16 {%0,%1}, [%2];"
                 : "=r"(r[0]), "=r"(r[1]) : "r"(addr));
}
__device__ __forceinline__ void mma_16816(float d[4], const unsigned a[4], unsigned b0, unsigned b1) {
    asm volatile("mma.sync.aligned.m16n8k16.row.col.f32.f16.f16.f32 "
        "{%0,%1,%2,%3}, {%4,%5,%6,%7}, {%8,%9}, {%0,%1,%2,%3};"
        : "+f"(d[0]), "+f"(d[1]), "+f"(d[2]), "+f"(d[3])
        : "r"(a[0]), "r"(a[1]), "r"(a[2]), "r"(a[3]), "r"(b0), "r"(b1));
}
__device__ __forceinline__ float lrelu(float v) { return (v > 0.f) ? v : 0.01f * v; }

// ---------------- reset counters (graph-replay determinism) ----------------
__global__ void reset_kernel() {
    if (threadIdx.x < BB) g_done[threadIdx.x] = 0;
    if (threadIdx.x == BB) g_prep = 0;
}

// ---------------- mega kernel: interleaved transpose-role + fused-role ----------------
__global__ __launch_bounds__(THREADS, 2)
void maf_mega(const float* __restrict__ sf,
              const float* __restrict__ W0f, const float* __restrict__ W1f,
              const float* __restrict__ W2f,
              const float* __restrict__ p, const float* __restrict__ cam,
              const float* __restrict__ b0, const float* __restrict__ b1,
              const float* __restrict__ b2, float* __restrict__ out)
{
    extern __shared__ char smem[];
    const int bid  = blockIdx.x;
    const int tid  = threadIdx.x;
    const int warp = tid >> 5;
    const int lane = tid & 31;

    const int fidx = bid / 7;
    const int rmod = bid - fidx * 7;
    const bool is_fused = (rmod == 6) && (fidx < FTILES);

    if (!is_fused) {
        // ================= transpose role =================
        const int t = bid - min(fidx, FTILES);       // 0..3583
        const int b = t / 56;
        const int w = t - b * 56;
        const int y = w / 7;                          // ch group (32 ch)
        const int x = w - y * 7;                      // px super-group (7 x 64 px)
        const int c0 = y * 32;

        // weight prep over first 234 transpose blocks (59904 = 234*256)
        if (t < 234) {
            int i = t * 256 + tid;
            if (i < 32768) {
                int o = i >> 8, k = i & 255;
                *(__half*)(g_W0s + (k >> 6) * 16384 + tile_off(o, k & 63, 128)) =
                    __float2half(W0f[o * 256 + k]);
            } else if (i < 32768 + 24576) {
                int j = i - 32768, o = j / 384, k = j - o * 384;
                *(__half*)(g_W1s + (k >> 7) * 16384 + tile_off(o, k & 127, 256)) =
                    __float2half(W1f[o * 384 + k]);
            } else {
                int j = i - 32768 - 24576, o = j / 320, k = j - o * 320;
                float v = (o < 5) ? W2f[o * 320 + k] : 0.f;
                *(__half*)(g_W2s + tile_off(o, k, 640)) = __float2half(v);
            }
        }

        float (*tile)[32][65] = (float(*)[32][65])smem;   // 7 x 32 x 65 f32 = 58240B
        const float* src = sf + (size_t)b * CC * HW;
        // loads: 7 sub-tiles x 512 float4 = 3584 over 256 threads (14 each, independent)
        #pragma unroll
        for (int it = 0; it < 14; it++) {
            int e   = tid + it * 256;
            int sub = e >> 9;
            int ww  = e & 511;
            int ch  = ww >> 4;
            int f4  = ww & 15;
            float4 v = *(const float4*)(src + (size_t)(c0 + ch) * HW + (x * 7 + sub) * 64 + f4 * 4);
            tile[sub][ch][f4 * 4 + 0] = v.x;
            tile[sub][ch][f4 * 4 + 1] = v.y;
            tile[sub][ch][f4 * 4 + 2] = v.z;
            tile[sub][ch][f4 * 4 + 3] = v.w;
        }
        __syncthreads();
        // stores: per sub, thread -> (px = tid>>2, q = tid&3), one uint4 (proven mapping)
        const int px = tid >> 2;
        const int q  = tid & 3;
        #pragma unroll
        for (int sub = 0; sub < 7; sub++) {
            __half2 h[4];
            #pragma unroll
            for (int s = 0; s < 4; s++)
                h[s] = __floats2half2_rn(tile[sub][q * 8 + 2 * s][px],
                                         tile[sub][q * 8 + 2 * s + 1][px]);
            uint4* dst = (uint4*)(g_sfT + (size_t)b * HW * CC +
                                  (size_t)((x * 7 + sub) * 64 + px) * CC + c0);
            dst[q] = *(uint4*)h;
        }
        // publish: all threads fence, barrier, then tid0 arrives
        __threadfence();
        __syncthreads();
        if (tid == 0) {
            atomicAdd(&g_done[b], 1);
            if (t < 234) atomicAdd(&g_prep, 1);
        }
        return;
    }

    // ================= fused role =================
    const unsigned sbase = smem_u32(smem);
    const int tile = fidx;

    // wait for weight prep + source images
    {
        const int b0i = (tile * TILE_P) / NN;
        const int b1i = min(tile * TILE_P + TILE_P - 1, NPTS - 1) / NN;
        if (tid == 0) {
            while (atomicAdd(&g_prep, 0) < 234) __nanosleep(200);
            while (atomicAdd(&g_done[b0i], 0) < 56) __nanosleep(200);
            while (atomicAdd(&g_done[b1i], 0) < 56) __nanosleep(200);
        }
        __syncthreads();
        __threadfence();
    }

    // group 0: W2 (320 x 16B lines) + W0 chunk0
    {
        if (tid < 64) {
            #pragma unroll
            for (int i = 0; i < 5; i++)
                cp_async16(sbase + SM_W2 + (tid + i * 64) * 16, g_W2s + (tid + i * 64) * 16);
        }
        #pragma unroll
        for (int i = 0; i < 4; i++)
            cp_async16(sbase + SM_BUF + (tid + i * 256) * 16, g_W0s + (tid + i * 256) * 16);
        asm volatile("cp.async.commit_group;");
    }

    // point params -> smem scratch (in y0 region)
    float* pW   = (float*)(smem + PRM_W);
    int*   pOff = (int*)  (smem + PRM_OFF);
    if (tid < TILE_P) {
        int gp = tile * TILE_P + tid;
        if (gp >= NPTS) gp = NPTS - 1;
        const int b = gp / NN;
        float s  = cam[b * 3 + 0];
        float tx = cam[b * 3 + 1];
        float ty = cam[b * 3 + 2];
        float gx = (s * (p[gp * 3 + 0] + tx) + 1.f) * (0.5f * (WW - 1));
        float gy = (s * (p[gp * 3 + 1] + ty) + 1.f) * (0.5f * (HH - 1));
        float x0f = floorf(gx), y0f = floorf(gy);
        float wx1 = gx - x0f, wy1 = gy - y0f;
        float wx0 = 1.f - wx1, wy0 = 1.f - wy1;
        if (!(x0f       >= 0.f && x0f       <= (float)(WW - 1))) wx0 = 0.f;
        if (!(x0f + 1.f >= 0.f && x0f + 1.f <= (float)(WW - 1))) wx1 = 0.f;
        if (!(y0f       >= 0.f && y0f       <= (float)(HH - 1))) wy0 = 0.f;
        if (!(y0f + 1.f >= 0.f && y0f + 1.f <= (float)(HH - 1))) wy1 = 0.f;
        int ix0 = (int)fminf(fmaxf(x0f,       0.f), (float)(WW - 1));
        int ix1 = (int)fminf(fmaxf(x0f + 1.f, 0.f), (float)(WW - 1));
        int iy0 = (int)fminf(fmaxf(y0f,       0.f), (float)(HH - 1));
        int iy1 = (int)fminf(fmaxf(y0f + 1.f, 0.f), (float)(HH - 1));
        int base = b * HW;
        pOff[0 * TILE_P + tid] = (base + iy0 * WW + ix0) * CC;
        pOff[1 * TILE_P + tid] = (base + iy0 * WW + ix1) * CC;
        pOff[2 * TILE_P + tid] = (base + iy1 * WW + ix0) * CC;
        pOff[3 * TILE_P + tid] = (base + iy1 * WW + ix1) * CC;
        pW[0 * TILE_P + tid] = wx0 * wy0; pW[1 * TILE_P + tid] = wx1 * wy0;
        pW[2 * TILE_P + tid] = wx0 * wy1; pW[3 * TILE_P + tid] = wx1 * wy1;
    }
    __syncthreads();

    // gather: warp owns 6 points; per (point,corner) one full contiguous 512B row
    {
        const int p0i = warp * 6;
        #pragma unroll 2
        for (int i = 0; i < 6; i++) {
            const int pt = p0i + i;
            const float w00 = pW[0 * TILE_P + pt], w10 = pW[1 * TILE_P + pt];
            const float w01 = pW[2 * TILE_P + pt], w11 = pW[3 * TILE_P + pt];
            uint4 A  = *(const uint4*)(g_sfT + pOff[0 * TILE_P + pt] + lane * 8);
            uint4 Bv = *(const uint4*)(g_sfT + pOff[1 * TILE_P + pt] + lane * 8);
            uint4 Cv = *(const uint4*)(g_sfT + pOff[2 * TILE_P + pt] + lane * 8);
            uint4 Dv = *(const uint4*)(g_sfT + pOff[3 * TILE_P + pt] + lane * 8);
            __half2 hh[4];
            #pragma unroll
            for (int qq = 0; qq < 4; qq++) {
                float2 fa = __half22float2(((const __half2*)&A)[qq]);
                float2 fb = __half22float2(((const __half2*)&Bv)[qq]);
                float2 fc = __half22float2(((const __half2*)&Cv)[qq]);
                float2 fd = __half22float2(((const __half2*)&Dv)[qq]);
                float rx = w00 * fa.x + w10 * fb.x + w01 * fc.x + w11 * fd.x;
                float ry = w00 * fa.y + w10 * fb.y + w01 * fc.y + w11 * fd.y;
                hh[qq] = __floats2half2_rn(rx, ry);
            }
            *(uint4*)(smem + SM_FEAT + tile_off(pt, lane * 8, 512)) = *(uint4*)hh;
        }
    }

    const int qr = lane >> 2;
    const int qc = (lane & 3) * 2;
    const int ar = lane & 15, ak = (lane >> 4) * 8;
    const int br = (lane & 7) + ((lane >> 4) << 3), bk = ((lane >> 3) & 1) * 8;

    // ---------------- layer0: D0[48,128], K=256; warp = 48 rows x 16 outs ----------------
    float d0[3][2][4];
    #pragma unroll
    for (int i = 0; i < 3; i++)
        #pragma unroll
        for (int j = 0; j < 2; j++)
            #pragma unroll
            for (int qn = 0; qn < 4; qn++) d0[i][j][qn] = 0.f;
    {
        const int n0 = warp * 16;
        for (int c = 0; c < 4; c++) {
            if (c < 3)
                stage16k(sbase + SM_BUF + ((c + 1) & 1) * 16384, g_W0s + (c + 1) * 16384, tid);
            else
                stage16k(sbase + SM_BUF + 0 * 16384, g_W1s, tid);
            asm volatile("cp.async.wait_group 1;");
            __syncthreads();
            const unsigned bufc = sbase + SM_BUF + (c & 1) * 16384;
            #pragma unroll
            for (int k16 = 0; k16 < 4; k16++) {
                const int kg = c * 64 + k16 * 16;
                const int kl = k16 * 16;
                unsigned a[3][4];
                #pragma unroll
                for (int mt = 0; mt < 3; mt++)
                    ldm_x4(a[mt], sbase + SM_FEAT + tile_off(mt * 16 + ar, kg + ak, 512));
                unsigned bfr[4];
                ldm_x4(bfr, bufc + tile_off(n0 + br, kl + bk, 128));
                #pragma unroll
                for (int mt = 0; mt < 3; mt++) {
                    mma_16816(d0[mt][0], a[mt], bfr[0], bfr[1]);
                    mma_16816(d0[mt][1], a[mt], bfr[2], bfr[3]);
                }
            }
            __syncthreads();
        }
    }

    // epilogue0 -> y0 (stride 256)
    {
        const int n0 = warp * 16;
        #pragma unroll
        for (int mt = 0; mt < 3; mt++)
            #pragma unroll
            for (int nt = 0; nt < 2; nt++) {
                int row = mt * 16 + qr;
                int o   = n0 + nt * 8 + qc;
                float bx = __ldg(b0 + o), by = __ldg(b0 + o + 1);
                __half2 h0 = __floats2half2_rn(lrelu(d0[mt][nt][0] + bx), lrelu(d0[mt][nt][1] + by));
                __half2 h1 = __floats2half2_rn(lrelu(d0[mt][nt][2] + bx), lrelu(d0[mt][nt][3] + by));
                *(__half2*)(smem + SM_Y0 + tile_off(row,     o, 256)) = h0;
                *(__half2*)(smem + SM_Y0 + tile_off(row + 8, o, 256)) = h1;
            }
    }

    // ---------------- layer1: D1[48,64], K=384; warp = 48 rows x 8 outs ----------------
    float d1[3][4];
    #pragma unroll
    for (int i = 0; i < 3; i++)
        #pragma unroll
        for (int qn = 0; qn < 4; qn++) d1[i][qn] = 0.f;
    {
        const int n0w = warp * 8;
        const int b1r = lane & 7, b1k = ((lane >> 3) & 1) * 8;
        for (int c = 0; c < 3; c++) {
            if (c < 2) {
                stage16k(sbase + SM_BUF + ((c + 1) & 1) * 16384, g_W1s + (c + 1) * 16384, tid);
                asm volatile("cp.async.wait_group 1;");
            } else {
                asm volatile("cp.async.wait_group 0;");
            }
            __syncthreads();
            const unsigned bufc = sbase + SM_BUF + (c & 1) * 16384;
            const unsigned abase = (c == 0) ? (sbase + SM_Y0) : (sbase + SM_FEAT);
            const int S    = (c == 0) ? 256 : 512;
            const int kofs = (c == 2) ? 128 : 0;
            #pragma unroll
            for (int k16 = 0; k16 < 8; k16++) {
                const int kl = k16 * 16;
                unsigned a[3][4];
                #pragma unroll
                for (int mt = 0; mt < 3; mt++)
                    ldm_x4(a[mt], abase + tile_off(mt * 16 + ar, kofs + kl + ak, S));
                unsigned bfr[2];
                ldm_x2(bfr, bufc + tile_off(n0w + b1r, kl + b1k, 256));
                #pragma unroll
                for (int mt = 0; mt < 3; mt++)
                    mma_16816(d1[mt], a[mt], bfr[0], bfr[1]);
            }
            __syncthreads();
        }
    }

    // epilogue1 -> y1 (stride 128, aliases y0 region; all y0 reads complete)
    {
        const int n0w = warp * 8;
        #pragma unroll
        for (int mt = 0; mt < 3; mt++) {
            int row = mt * 16 + qr;
            int o   = n0w + qc;
            float bx = __ldg(b1 + o), by = __ldg(b1 + o + 1);
            __half2 h0 = __floats2half2_rn(lrelu(d1[mt][0] + bx), lrelu(d1[mt][1] + by));
            __half2 h1 = __floats2half2_rn(lrelu(d1[mt][2] + bx), lrelu(d1[mt][3] + by));
            *(__half2*)(smem + SM_Y1 + tile_off(row,     o, 128)) = h0;
            *(__half2*)(smem + SM_Y1 + tile_off(row + 8, o, 128)) = h1;
        }
    }
    __syncthreads();

    // ---------------- layer2: D2[48,8], K=320; warps 0..2 one m-tile each ----------------
    if (warp < 3) {
        float d2[4] = {0.f, 0.f, 0.f, 0.f};
        const int m0 = warp * 16;
        const int b2r = lane & 7, b2k = ((lane >> 3) & 1) * 8;
        #pragma unroll 4
        for (int k16 = 0; k16 < 20; k16++) {
            const int kk = k16 * 16;
            const unsigned abase = (kk < 64) ? (sbase + SM_Y1) : (sbase + SM_FEAT);
            const int S    = (kk < 64) ? 128 : 512;
            const int kloc = (kk < 64) ? kk : (kk - 64);
            unsigned a[4];
            ldm_x4(a, abase + tile_off(m0 + ar, kloc + ak, S));
            unsigned bfr[2];
            ldm_x2(bfr, sbase + SM_W2 + tile_off(b2r, kk + b2k, 640));
            mma_16816(d2, a, bfr[0], bfr[1]);
        }
        #pragma unroll
        for (int half = 0; half < 2; half++) {
            int pt = m0 + half * 8 + qr;
            int gp = tile * TILE_P + pt;
            if (gp < NPTS) {
                int b = gp / NN;
                int n = gp - b * NN;
                float v0 = d2[half * 2 + 0] + __ldg(b2 + qc);
                if (qc < 5)     out[b * (5 * NN) + qc * NN + n] = fmaxf(v0, 0.f);
                if (qc + 1 < 5) {
                    float v1 = d2[half * 2 + 1] + __ldg(b2 + qc + 1);
                    out[b * (5 * NN) + (qc + 1) * NN + n] = fmaxf(v1, 0.f);
                }
            }
        }
    }
}

extern "C" void kernel_launch(void* const* d_in, const int* in_sizes, int n_in,
                              void* d_out, int out_size) {
    const float* p   = (const float*)d_in[0];
    const float* cam = (const float*)d_in[1];
    const float* sf  = (const float*)d_in[2];
    const float* W0  = (const float*)d_in[3];
    const float* b0  = (const float*)d_in[4];
    const float* W1  = (const float*)d_in[5];
    const float* b1  = (const float*)d_in[6];
    const float* W2  = (const float*)d_in[7];
    const float* b2  = (const float*)d_in[8];
    float* out = (float*)d_out;

    reset_kernel<<<1, 128>>>();

    cudaFuncSetAttribute(maf_mega, cudaFuncAttributeMaxDynamicSharedMemorySize, SM_TOTAL);
    maf_mega<<<GRID_TOTAL, THREADS, SM_TOTAL>>>(sf, W0, W1, W2, p, cam, b0, b1, b2, out);
}